// round 16
// baseline (speedup 1.0000x reference)
#include <cuda_runtime.h>
#include <cuda_fp16.h>
#include <math.h>
#include <stdint.h>

// Problem constants
#define BATCH 2
#define SEQ   2048
#define CDIM  1024
#define NHEAD 16
#define HDIM  64
#define C3    (3*CDIM)          // 3072
#define MROWS (BATCH*SEQ)       // 4096

// All mma-operand tensors use a within-16 permutation pi on their k-dim:
//   logical (2t,2t+1) -> stored (4t,4t+1);  logical (2t+8,2t+9) -> stored (4t+2,4t+3)
// so thread t's m16n8k16 fragment halves are 4 contiguous stored halves (LDS/LDG.64).
__device__ __host__ __forceinline__ int pi16(int o) {   // o in [0,16)
    return 4 * ((o & 7) >> 1) + 2 * ((o >> 3) & 1) + (o & 1);
}

// Scratch (no cudaMalloc allowed)
__device__ __half g_qkvh[(size_t)MROWS * C3];      // [B,T,3,H,D] fp16, d pi-stored
__device__ __half g_vT[(size_t)BATCH * NHEAD * HDIM * SEQ]; // V^T [b][h][d][t], t pi-stored
__device__ __half g_attnh[(size_t)MROWS * CDIM];   // attention out fp16, CDIM pi-stored
__device__ __half g_xh[(size_t)MROWS * CDIM];      // x fp16, CDIM pi-stored
__device__ __half g_wqkvT[(size_t)C3 * CDIM];      // Wqkv^T [3072][1024], K pi-stored
__device__ __half g_woutT[(size_t)CDIM * CDIM];    // Wout^T, K pi-stored

__device__ __forceinline__ uint32_t smem_u32(const void* p) {
    uint32_t a;
    asm("{ .reg .u64 t; cvta.to.shared.u64 t, %1; cvt.u32.u64 %0, t; }" : "=r"(a) : "l"(p));
    return a;
}
__device__ __forceinline__ uint32_t pack_h2(float a, float b) {
    __half2 h = __floats2half2_rn(a, b);
    return *(uint32_t*)&h;
}
__device__ __forceinline__ uint32_t exp2_h2(float a, float b) {
    uint32_t x = pack_h2(a, b);
    uint32_t y;
    asm("ex2.approx.f16x2 %0, %1;" : "=r"(y) : "r"(x));
    return y;
}
#define CP_ASYNC16(dst_u32, src_ptr) \
    asm volatile("cp.async.cg.shared.global [%0], [%1], 16;" :: "r"(dst_u32), "l"(src_ptr) : "memory")
#define CP_COMMIT() asm volatile("cp.async.commit_group;" ::: "memory")
#define CP_WAIT0()  asm volatile("cp.async.wait_group 0;" ::: "memory")
#define CP_WAIT1()  asm volatile("cp.async.wait_group 1;" ::: "memory")

// m16n8k16 fp16 mma, fp32 accumulate
__device__ __forceinline__ void mma_f16(float c[4], const uint32_t a[4], const uint32_t b0, const uint32_t b1) {
    asm volatile(
        "mma.sync.aligned.m16n8k16.row.col.f32.f16.f16.f32 "
        "{%0,%1,%2,%3}, {%4,%5,%6,%7}, {%8,%9}, {%0,%1,%2,%3};"
        : "+f"(c[0]), "+f"(c[1]), "+f"(c[2]), "+f"(c[3])
        : "r"(a[0]), "r"(a[1]), "r"(a[2]), "r"(a[3]), "r"(b0), "r"(b1));
}

// ---------------------------------------------------------------------------
// Fused pre-pass: Wqkv^T, Wout^T (transpose + fp16 + pi), x -> fp16 + pi
// ---------------------------------------------------------------------------
#define WQ_BLOCKS ((C3/32)*(CDIM/32))       // 3072
#define WO_BLOCKS ((CDIM/32)*(CDIM/32))     // 1024
#define XC_N16    (MROWS * CDIM / 16)       // 262144 (16-half pi-groups)
#define XC_BLOCKS ((XC_N16 + 255) / 256)    // 1024
#define PRE_BLOCKS (WQ_BLOCKS + WO_BLOCKS + XC_BLOCKS)

__global__ __launch_bounds__(256)
void prepass_kernel(const float* __restrict__ x,    __half* __restrict__ xh,
                    const float* __restrict__ wq,   __half* __restrict__ wqT,
                    const float* __restrict__ wo,   __half* __restrict__ woT)
{
    const int bid = blockIdx.x;
    if (bid < WQ_BLOCKS + WO_BLOCKS) {
        const float* in; __half* out; int K, N, idx;
        if (bid < WQ_BLOCKS) { in = wq; out = wqT; K = CDIM; N = C3;   idx = bid; }
        else                 { in = wo; out = woT; K = CDIM; N = CDIM; idx = bid - WQ_BLOCKS; }
        const int nb32 = N / 32;
        const int n0 = (idx % nb32) * 32;
        const int k0 = (idx / nb32) * 32;
        __shared__ float tile[32][33];
        const int tx = threadIdx.x & 31;
        const int ty = threadIdx.x >> 5;
        #pragma unroll
        for (int i = 0; i < 32; i += 8)
            tile[ty + i][tx] = in[(size_t)(k0 + ty + i) * N + n0 + tx];
        __syncthreads();
        const int sk = k0 + (tx & 16) + pi16(tx & 15);   // pi-stored k index
        #pragma unroll
        for (int i = 0; i < 32; i += 8)
            out[(size_t)(n0 + ty + i) * K + sk] = __float2half_rn(tile[tx][ty + i]);
    } else {
        // x: one thread = one 16-float pi-group
        const int i = (bid - WQ_BLOCKS - WO_BLOCKS) * 256 + threadIdx.x;
        if (i >= XC_N16) return;
        float4 v0 = ((const float4*)x)[4 * i];
        float4 v1 = ((const float4*)x)[4 * i + 1];
        float4 v2 = ((const float4*)x)[4 * i + 2];
        float4 v3 = ((const float4*)x)[4 * i + 3];
        // pairs P0..P7 (logical); stored order: P0,P4,P1,P5 | P2,P6,P3,P7
        uint4 u0, u1;
        u0.x = pack_h2(v0.x, v0.y);   // P0
        u0.y = pack_h2(v2.x, v2.y);   // P4
        u0.z = pack_h2(v0.z, v0.w);   // P1
        u0.w = pack_h2(v2.z, v2.w);   // P5
        u1.x = pack_h2(v1.x, v1.y);   // P2
        u1.y = pack_h2(v3.x, v3.y);   // P6
        u1.z = pack_h2(v1.z, v1.w);   // P3
        u1.w = pack_h2(v3.z, v3.w);   // P7
        ((uint4*)xh)[2 * i]     = u0;
        ((uint4*)xh)[2 * i + 1] = u1;
    }
}

// ---------------------------------------------------------------------------
// V transpose: g_vT[b][h][d][t] (t pi-stored within 16) from g_qkvh V-part.
// Note: qkvh's d-dim pi does NOT matter here; we read whole 4-half chunks of d
// and transpose element-wise, carrying stored-d order through (V's n-dim order
// just has to match the attention epilogue's d order, which reads logical O
// columns; so we must UNDO qkvh's d-pi when indexing d here).
// Simplest correct approach: read d in stored order, emit rows at stored-d
// index; attention PV then produces O columns in stored-d order; the epilogue
// writes attnh at pi(stored-d)??  -- to avoid double-permutation confusion we
// instead UN-pi the d index here so vT rows are LOGICAL d.
// ---------------------------------------------------------------------------
__global__ __launch_bounds__(256)
void vtrans_kernel(const __half* __restrict__ qkvh, __half* __restrict__ vT)
{
    __shared__ __half tile[64][68];
    const int tb = blockIdx.x * 64;
    const int bh = blockIdx.y;
    const int b  = bh >> 4;
    const int h  = bh & 15;
    const int tid = threadIdx.x;
    const int rr = tid >> 4;         // 0..15
    const int c4 = (tid & 15) * 4;   // 0..60  (stored-d chunk)
    // load stored-d chunks, scatter into tile at LOGICAL d
    // stored s (within 16): logical o: inverse of pi16. Build per-chunk.
    #pragma unroll
    for (int it = 0; it < 4; it++) {
        const int tt = it * 16 + rr;
        const __half* src = qkvh + (size_t)(b * SEQ + tb + tt) * C3 + 2 * CDIM + h * HDIM + c4;
        uint2 v = *(const uint2*)src;
        __half hv[4];
        *(uint2*)hv = v;
        const int base16 = c4 & ~15;
        #pragma unroll
        for (int q = 0; q < 4; q++) {
            const int s = (c4 & 15) + q;                       // stored pos within 16
            // inverse pi: stored 4t+e -> logical 2t+e ; stored 4t+2+e -> logical 8+2t+e
            const int tq = s >> 2, rem = s & 3;
            const int logical = (rem < 2) ? (2 * tq + rem) : (8 + 2 * tq + (rem - 2));
            tile[tt][base16 + logical] = hv[q];
        }
    }
    __syncthreads();
    // write vT rows = logical d; key dim pi-stored within 16
    #pragma unroll
    for (int it = 0; it < 4; it++) {
        const int d = it * 16 + rr;
        __half vals[4];
        #pragma unroll
        for (int q = 0; q < 4; q++) vals[q] = tile[c4 + q][d];   // keys tb+c4+q (logical)
        // logical key pairs (c4,c4+1) and (c4+2,c4+3) -> stored s1, s1+4
        const int o4 = (c4 >> 2) & 3;
        const int s1 = ((o4 & 1) << 3) | ((o4 >> 1) << 1);       // {0,8,2,10}
        __half* dst = vT + ((size_t)(b * NHEAD + h) * HDIM + d) * SEQ + tb + (c4 & ~15);
        *(uint32_t*)(dst + s1)     = *(uint32_t*)&vals[0];
        *(uint32_t*)(dst + s1 + 4) = *(uint32_t*)&vals[2];
    }
}

// ---------------------------------------------------------------------------
// fp16 mma GEMM + bias, k-grouped smem [ksgroup][row][16] with pi -> LDS.64.
// C[M,N] = A[M,K] @ Bt[N,K]^T + bias[N]. A,Bt global pi-stored on K.
// CTA 128x128, BK=64, 8 warps (2x4), warp tile 64x32.
// RND=true: C is __half written pi-stored on N (feeds later mma stages).
// ---------------------------------------------------------------------------
#define GBM 128
#define GBN 128
#define GBK 64
#define KG_HALVES 2048                    // one ksgroup: 128 rows x 16 halves
#define TILE_HALVES (4 * KG_HALVES)       // 8192
#define STG_HALVES (2 * TILE_HALVES)      // 16384
#define GEMM_SMEM (3 * STG_HALVES * 2)    // 98304 B

template<bool RND>
__global__ __launch_bounds__(256)
void gemm_h_kernel(const __half* __restrict__ A,
                   const __half* __restrict__ Bt,
                   const float* __restrict__ bias,
                   void* __restrict__ Cv,
                   int M, int N, int K)
{
    extern __shared__ char smem_raw[];
    __half* smem = (__half*)smem_raw;
    const int tid = threadIdx.x;
    const int wid = tid >> 5;
    const int l   = tid & 31;
    const int warpM = wid >> 2;
    const int warpN = wid & 3;
    const int g = l >> 2;
    const int t = l & 3;
    const int rowbase = blockIdx.y * GBM;
    const int colbase = blockIdx.x * GBN;

    const uint32_t smb = smem_u32(smem);

    float acc[4][4][4];
    #pragma unroll
    for (int i = 0; i < 4; i++)
        #pragma unroll
        for (int j = 0; j < 4; j++)
            #pragma unroll
            for (int q = 0; q < 4; q++) acc[i][j][q] = 0.f;

    const int S = K / GBK;

    // loader: chunk idx -> r = idx/8, c8 = (idx%8)*8; smem dst (ksg, r, hh)
    auto load_stage = [&](int stg, int k0) {
        const uint32_t sa = smb + (uint32_t)(stg * STG_HALVES) * 2;
        const uint32_t sb = sa + (uint32_t)TILE_HALVES * 2;
        #pragma unroll
        for (int it = 0; it < 4; it++) {
            const int idx = it * 256 + tid;
            const int r  = idx >> 3;
            const int c8 = (idx & 7) * 8;
            const int ksg = c8 >> 4;
            const int hh  = c8 & 15;
            const uint32_t doff = (uint32_t)(ksg * KG_HALVES + r * 16 + hh) * 2;
            CP_ASYNC16(sa + doff, A  + (size_t)(rowbase + r) * K + k0 + c8);
            CP_ASYNC16(sb + doff, Bt + (size_t)(colbase + r) * K + k0 + c8);
        }
        CP_COMMIT();
    };

    load_stage(0, 0);
    load_stage(1, GBK);

    const int arow0 = warpM * 64 + g;
    const int bcol0 = warpN * 32 + g;

    for (int s = 0; s < S; s++) {
        if (s + 1 < S) { CP_WAIT1(); } else { CP_WAIT0(); }
        __syncthreads();
        if (s + 2 < S) load_stage((s + 2) % 3, (s + 2) * GBK);

        const __half* as = smem + (s % 3) * STG_HALVES;
        const __half* bs = as + TILE_HALVES;
        #pragma unroll
        for (int ks = 0; ks < 4; ks++) {
            const __half* ak = as + ks * KG_HALVES + 4 * t;
            const __half* bk = bs + ks * KG_HALVES + 4 * t;
            uint32_t af[4][4];
            uint2 bf[4];
            #pragma unroll
            for (int i = 0; i < 4; i++) {
                const int r = arow0 + i * 16;
                uint2 lo = *(const uint2*)(ak + r * 16);
                uint2 hi = *(const uint2*)(ak + (r + 8) * 16);
                af[i][0] = lo.x; af[i][1] = hi.x;
                af[i][2] = lo.y; af[i][3] = hi.y;
            }
            #pragma unroll
            for (int j = 0; j < 4; j++)
                bf[j] = *(const uint2*)(bk + (bcol0 + j * 8) * 16);
            #pragma unroll
            for (int i = 0; i < 4; i++)
                #pragma unroll
                for (int j = 0; j < 4; j++)
                    mma_f16(acc[i][j], af[i], bf[j].x, bf[j].y);
        }
    }

    const int erow = rowbase + warpM * 64 + g;
    #pragma unroll
    for (int i = 0; i < 4; i++) {
        #pragma unroll
        for (int j = 0; j < 4; j++) {
            const int r0 = erow + i * 16;
            const int c0 = colbase + warpN * 32 + j * 8 + 2 * t;   // logical col
            const float b0 = bias[c0], b1 = bias[c0 + 1];
            if (RND) {
                // pi-stored column for the pair
                const int sc0 = colbase + warpN * 32 + (j >> 1) * 16 + 4 * t + 2 * (j & 1);
                __half* C = (__half*)Cv;
                *(uint32_t*)(C + (size_t)r0 * N + sc0)       = pack_h2(acc[i][j][0] + b0, acc[i][j][1] + b1);
                *(uint32_t*)(C + (size_t)(r0 + 8) * N + sc0) = pack_h2(acc[i][j][2] + b0, acc[i][j][3] + b1);
            } else {
                float* C = (float*)Cv;
                float2 v0 = { acc[i][j][0] + b0, acc[i][j][1] + b1 };
                float2 v1 = { acc[i][j][2] + b0, acc[i][j][3] + b1 };
                *(float2*)(C + (size_t)r0 * N + c0)       = v0;
                *(float2*)(C + (size_t)(r0 + 8) * N + c0) = v1;
            }
        }
    }
}

// ---------------------------------------------------------------------------
// fp16 flash attention: k-grouped pi smem (LDS.64 fragments), register-direct
// P, f16x2 exp, ones-row l, packed max-reduce, vote-gated rescale.
// K smem [dgroup(4)][key(64)][16]; V smem [keygroup(4)][d(72)][16].
// ---------------------------------------------------------------------------
#define AQ 128
#define AK 64
#define K_HALVES (4 * 64 * 16)             // 4096
#define VG_HALVES (72 * 16)                // 1152 per key-group
#define V_HALVES (4 * VG_HALVES)           // 4608 (rows 64-71 = ones/zeros pad)
#define KV_HALVES (K_HALVES + V_HALVES)    // 8704 per stage
#define ATTN_SMEM (2 * KV_HALVES * 2)      // 34816 B

__global__ __launch_bounds__(256, 2)
void attn_h_kernel(const __half* __restrict__ qkv, const __half* __restrict__ vT,
                   __half* __restrict__ out)
{
    extern __shared__ char smem_raw[];
    __half* sm = (__half*)smem_raw;

    const int qtile = gridDim.x - 1 - blockIdx.x;   // heavy tiles first
    const int h   = blockIdx.y;
    const int b   = blockIdx.z;
    const int tid = threadIdx.x;
    const int wid = tid >> 5;
    const int l   = tid & 31;
    const int g   = l >> 2;
    const int t   = l & 3;
    const int qb  = qtile * AQ;
    const int rg  = qb + wid * 16 + g;

    const float SC = 0.18033688011112042f;   // (1/sqrt(64)) * log2(e)
    const uint32_t smb = smem_u32(sm);

    auto load_kv = [&](int stg, int kb) {
        const uint32_t kbuf = smb + (uint32_t)(stg * KV_HALVES) * 2;
        const uint32_t vbuf = kbuf + (uint32_t)K_HALVES * 2;
        #pragma unroll
        for (int it = 0; it < 2; it++) {
            const int idx = it * 256 + tid;
            const int r  = idx >> 3;           // 0..63
            const int c8 = (idx & 7) * 8;      // 0..56
            const int grp = c8 >> 4;
            const int hh  = c8 & 15;
            // K: key row r, d chunk c8 (d pi-stored in qkv)
            CP_ASYNC16(kbuf + (uint32_t)(grp * 1024 + r * 16 + hh) * 2,
                       qkv + (size_t)(b * SEQ + kb + r) * C3 + CDIM + h * HDIM + c8);
            // V: d row r, key chunk c8 (keys pi-stored in vT)
            CP_ASYNC16(vbuf + (uint32_t)(grp * VG_HALVES + r * 16 + hh) * 2,
                       vT + ((size_t)(b * NHEAD + h) * HDIM + r) * SEQ + kb + c8);
        }
        CP_COMMIT();
    };

    // Q fragments (qkv d-dim pi-stored: 4 contiguous halves per row per ks)
    uint32_t qa[4][4];
    {
        const __half* Qr  = qkv + (size_t)(b * SEQ + rg    ) * C3 + h * HDIM;
        const __half* Qr8 = qkv + (size_t)(b * SEQ + rg + 8) * C3 + h * HDIM;
        #pragma unroll
        for (int ks = 0; ks < 4; ks++) {
            uint2 q0 = *(const uint2*)(Qr  + ks * 16 + 4 * t);
            uint2 q8 = *(const uint2*)(Qr8 + ks * 16 + 4 * t);
            float2 f;
            f = __half22float2(*(__half2*)&q0.x); qa[ks][0] = pack_h2(f.x * SC, f.y * SC);
            f = __half22float2(*(__half2*)&q8.x); qa[ks][1] = pack_h2(f.x * SC, f.y * SC);
            f = __half22float2(*(__half2*)&q0.y); qa[ks][2] = pack_h2(f.x * SC, f.y * SC);
            f = __half22float2(*(__half2*)&q8.y); qa[ks][3] = pack_h2(f.x * SC, f.y * SC);
        }
    }

    // O[0..7] = output blocks; O[8] = l accumulator (ones-row of V)
    float O[9][4];
    #pragma unroll
    for (int nb = 0; nb < 9; nb++)
        #pragma unroll
        for (int q = 0; q < 4; q++) O[nb][q] = 0.f;
    float m0 = -INFINITY, m1 = -INFINITY;

    const int ntiles = (qb + AQ) / AK;

    load_kv(0, 0);
    if (ntiles > 1) load_kv(1, AK);

    // Init V pad rows 64-71 per key-group per stage (cp.async never writes them):
    // row 64 = 1.0 (ones for row-sum), rows 65-71 = 0. 2stg x 4grp x 8rows x 2 u4.
    if (tid < 128) {
        const int stage = tid >> 6;
        const int rem = tid & 63;
        const int grp = rem >> 4;
        const int row = 64 + ((rem >> 1) & 7);
        const int hh  = (rem & 1) * 8;
        const uint32_t ones2 = 0x3C003C00u;
        uint32_t v = (row == 64) ? ones2 : 0u;
        const uint32_t addr = smb + (uint32_t)(stage * KV_HALVES + K_HALVES
                              + grp * VG_HALVES + row * 16 + hh) * 2;
        asm volatile("st.shared.v4.b32 [%0], {%1,%2,%3,%4};"
                     :: "r"(addr), "r"(v), "r"(v), "r"(v), "r"(v) : "memory");
    }

    for (int ti = 0; ti < ntiles; ti++) {
        if (ti + 1 < ntiles) { CP_WAIT1(); } else { CP_WAIT0(); }
        __syncthreads();

        const __half* Ksm = sm + (ti & 1) * KV_HALVES;
        const __half* Vsm = Ksm + K_HALVES;
        const int kb = ti * AK;

        // S = Q @ K^T (scaled, log2 domain); K B-frags via LDS.64
        float sc[8][4];
        #pragma unroll
        for (int nb = 0; nb < 8; nb++) {
            sc[nb][0] = 0.f; sc[nb][1] = 0.f; sc[nb][2] = 0.f; sc[nb][3] = 0.f;
        }
        #pragma unroll
        for (int ks = 0; ks < 4; ks++) {
            const __half* kk = Ksm + ks * 1024 + 4 * t;
            #pragma unroll
            for (int nb = 0; nb < 8; nb++) {
                uint2 bf = *(const uint2*)(kk + (nb * 8 + g) * 16);
                mma_f16(sc[nb], qa[ks], bf.x, bf.y);
            }
        }

        const bool needmask = (kb + AK - 1) > (qb + wid * 16);
        float tm0 = -INFINITY, tm1 = -INFINITY;
        if (needmask) {
            #pragma unroll
            for (int nb = 0; nb < 8; nb++) {
                const int k0 = kb + nb * 8 + 2 * t;
                if (k0     > rg    ) sc[nb][0] = -INFINITY;
                if (k0 + 1 > rg    ) sc[nb][1] = -INFINITY;
                if (k0     > rg + 8) sc[nb][2] = -INFINITY;
                if (k0 + 1 > rg + 8) sc[nb][3] = -INFINITY;
                tm0 = fmaxf(tm0, fmaxf(sc[nb][0], sc[nb][1]));
                tm1 = fmaxf(tm1, fmaxf(sc[nb][2], sc[nb][3]));
            }
        } else {
            #pragma unroll
            for (int nb = 0; nb < 8; nb++) {
                tm0 = fmaxf(tm0, fmaxf(sc[nb][0], sc[nb][1]));
                tm1 = fmaxf(tm1, fmaxf(sc[nb][2], sc[nb][3]));
            }
        }
        {
            __half2 tm = __floats2half2_rn(tm0, tm1);
            __half2 o1 = __shfl_xor_sync(0xffffffffu, tm, 1);
            tm = __hmax2(tm, o1);
            __half2 o2 = __shfl_xor_sync(0xffffffffu, tm, 2);
            tm = __hmax2(tm, o2);
            float2 tmf = __half22float2(tm);
            tm0 = tmf.x; tm1 = tmf.y;
        }

        const float nm0 = fmaxf(m0, tm0);
        const float nm1 = fmaxf(m1, tm1);
        const bool upd = (nm0 != m0) || (nm1 != m1);
        if (__any_sync(0xffffffffu, upd)) {
            const uint32_t ch2 = exp2_h2(m0 - nm0, m1 - nm1);
            __half2 chh = *(__half2*)&ch2;
            float2 cf = __half22float2(chh);
            const float c0 = cf.x, c1 = cf.y;
            #pragma unroll
            for (int nb = 0; nb < 9; nb++) {
                O[nb][0] *= c0; O[nb][1] *= c0;
                O[nb][2] *= c1; O[nb][3] *= c1;
            }
            m0 = nm0; m1 = nm1;
        }

        // p = exp2(s - m) in fp16x2, direct A-fragments
        uint32_t pf[8][2];
        #pragma unroll
        for (int nb = 0; nb < 8; nb++) {
            pf[nb][0] = exp2_h2(sc[nb][0] - m0, sc[nb][1] - m0);
            pf[nb][1] = exp2_h2(sc[nb][2] - m1, sc[nb][3] - m1);
        }

        // O += P @ V  (V B-frags via LDS.64; block 8 = l via ones-row)
        #pragma unroll
        for (int ks = 0; ks < 4; ks++) {
            const __half* vk = Vsm + ks * VG_HALVES + 4 * t;
            uint32_t pa[4];
            pa[0] = pf[2 * ks    ][0];
            pa[1] = pf[2 * ks    ][1];
            pa[2] = pf[2 * ks + 1][0];
            pa[3] = pf[2 * ks + 1][1];
            #pragma unroll
            for (int nb = 0; nb < 9; nb++) {
                uint2 bf = *(const uint2*)(vk + (nb * 8 + g) * 16);
                mma_f16(O[nb], pa, bf.x, bf.y);
            }
        }
        __syncthreads();
        if (ti + 2 < ntiles) load_kv(ti & 1, (ti + 2) * AK);
    }

    // l at PV output column 64 -> group-leader lanes' O[8][0]/O[8][2]
    const float l0 = __shfl_sync(0xffffffffu, O[8][0], l & 0x1c);
    const float l1 = __shfl_sync(0xffffffffu, O[8][2], l & 0x1c);
    const float inv0 = 1.f / l0;
    const float inv1 = 1.f / l1;

    // Write attnh pi-stored on CDIM (feeds GEMM3 A-loads)
    __half* out0 = out + (size_t)(b * SEQ + rg    ) * CDIM + h * HDIM;
    __half* out8 = out + (size_t)(b * SEQ + rg + 8) * CDIM + h * HDIM;
    #pragma unroll
    for (int nb = 0; nb < 8; nb++) {
        const int scol = (nb >> 1) * 16 + 4 * t + 2 * (nb & 1);
        *(uint32_t*)(out0 + scol) = pack_h2(O[nb][0] * inv0, O[nb][1] * inv0);
        *(uint32_t*)(out8 + scol) = pack_h2(O[nb][2] * inv1, O[nb][3] * inv1);
    }
}

// ---------------------------------------------------------------------------
// Launch
// ---------------------------------------------------------------------------
extern "C" void kernel_launch(void* const* d_in, const int* in_sizes, int n_in,
                              void* d_out, int out_size)
{
    const float* x    = (const float*)d_in[0];
    const float* Wqkv = (const float*)d_in[1];
    const float* bqkv = (const float*)d_in[2];
    const float* Wout = (const float*)d_in[3];
    const float* bout = (const float*)d_in[4];
    float* out = (float*)d_out;

    __half *qkvh, *vT, *attnh, *xh, *wqkvT, *woutT;
    cudaGetSymbolAddress((void**)&qkvh,  g_qkvh);
    cudaGetSymbolAddress((void**)&vT,    g_vT);
    cudaGetSymbolAddress((void**)&attnh, g_attnh);
    cudaGetSymbolAddress((void**)&xh,    g_xh);
    cudaGetSymbolAddress((void**)&wqkvT, g_wqkvT);
    cudaGetSymbolAddress((void**)&woutT, g_woutT);

    static bool attr_set = false;
    if (!attr_set) {
        cudaFuncSetAttribute(gemm_h_kernel<true>,  cudaFuncAttributeMaxDynamicSharedMemorySize, GEMM_SMEM);
        cudaFuncSetAttribute(gemm_h_kernel<false>, cudaFuncAttributeMaxDynamicSharedMemorySize, GEMM_SMEM);
        cudaFuncSetAttribute(attn_h_kernel, cudaFuncAttributeMaxDynamicSharedMemorySize, ATTN_SMEM);
        attr_set = true;
    }

    // 0) Fused pre-pass: weights -> fp16 transposed + pi; x -> fp16 + pi
    prepass_kernel<<<PRE_BLOCKS, 256>>>(x, xh, Wqkv, wqkvT, Wout, woutT);

    // 1) QKV projection -> fp16, N pi-stored
    {
        dim3 grid(C3 / GBN, MROWS / GBM);
        gemm_h_kernel<true><<<grid, 256, GEMM_SMEM>>>(xh, wqkvT, bqkv, qkvh, MROWS, C3, CDIM);
    }
    // 1b) V transpose -> [b][h][d][t], keys pi-stored
    {
        dim3 grid(SEQ / 64, BATCH * NHEAD);
        vtrans_kernel<<<grid, 256>>>(qkvh, vT);
    }
    // 2) Causal flash attention -> fp16, CDIM pi-stored
    {
        dim3 grid(SEQ / AQ, NHEAD, BATCH);
        attn_h_kernel<<<grid, 256, ATTN_SMEM>>>(qkvh, vT, attnh);
    }
    // 3) Output projection -> fp32 (logical layout)
    {
        dim3 grid(CDIM / GBN, MROWS / GBM);
        gemm_h_kernel<false><<<grid, 256, GEMM_SMEM>>>(attnh, woutT, bout, out, MROWS, CDIM, CDIM);
    }
}

// round 17
// speedup vs baseline: 1.1679x; 1.1679x over previous
#include <cuda_runtime.h>
#include <cuda_fp16.h>
#include <math.h>
#include <stdint.h>

// Problem constants
#define BATCH 2
#define SEQ   2048
#define CDIM  1024
#define NHEAD 16
#define HDIM  64
#define C3    (3*CDIM)          // 3072
#define MROWS (BATCH*SEQ)       // 4096

// Scratch (no cudaMalloc allowed)
__device__ __half g_qkvh[(size_t)MROWS * C3];      // [B,T,3,H,D] fp16
__device__ __half g_vT[(size_t)BATCH * NHEAD * HDIM * SEQ]; // V^T [b][h][d][t]
__device__ __half g_attnh[(size_t)MROWS * CDIM];   // attention out fp16
__device__ __half g_xh[(size_t)MROWS * CDIM];      // x fp16
__device__ __half g_wqkvT[(size_t)C3 * CDIM];      // Wqkv^T [3072][1024] fp16
__device__ __half g_woutT[(size_t)CDIM * CDIM];    // Wout^T fp16

__device__ __forceinline__ uint32_t smem_u32(const void* p) {
    uint32_t a;
    asm("{ .reg .u64 t; cvta.to.shared.u64 t, %1; cvt.u32.u64 %0, t; }" : "=r"(a) : "l"(p));
    return a;
}
__device__ __forceinline__ uint32_t pack_h2(float a, float b) {
    __half2 h = __floats2half2_rn(a, b);
    return *(uint32_t*)&h;
}
__device__ __forceinline__ uint32_t exp2_h2(float a, float b) {
    uint32_t x = pack_h2(a, b);
    uint32_t y;
    asm("ex2.approx.f16x2 %0, %1;" : "=r"(y) : "r"(x));
    return y;
}
#define CP_ASYNC16(dst_u32, src_ptr) \
    asm volatile("cp.async.cg.shared.global [%0], [%1], 16;" :: "r"(dst_u32), "l"(src_ptr) : "memory")
#define CP_COMMIT() asm volatile("cp.async.commit_group;" ::: "memory")
#define CP_WAIT0()  asm volatile("cp.async.wait_group 0;" ::: "memory")
#define CP_WAIT1()  asm volatile("cp.async.wait_group 1;" ::: "memory")

// m16n8k16 fp16 mma, fp32 accumulate
__device__ __forceinline__ void mma_f16(float c[4], const uint32_t a[4], const uint32_t b0, const uint32_t b1) {
    asm volatile(
        "mma.sync.aligned.m16n8k16.row.col.f32.f16.f16.f32 "
        "{%0,%1,%2,%3}, {%4,%5,%6,%7}, {%8,%9}, {%0,%1,%2,%3};"
        : "+f"(c[0]), "+f"(c[1]), "+f"(c[2]), "+f"(c[3])
        : "r"(a[0]), "r"(a[1]), "r"(a[2]), "r"(a[3]), "r"(b0), "r"(b1));
}

// ---------------------------------------------------------------------------
// Pre-pass A (stream 0): Wqkv^T (transpose+fp16) + x -> fp16
// ---------------------------------------------------------------------------
#define WQ_BLOCKS ((C3/32)*(CDIM/32))       // 3072
#define XC_N8     (MROWS * CDIM / 8)        // 524288
#define XC_BLOCKS ((XC_N8 + 255) / 256)     // 2048
#define PREM_BLOCKS (WQ_BLOCKS + XC_BLOCKS)

__global__ __launch_bounds__(256)
void prepass_main_kernel(const float* __restrict__ x,  __half* __restrict__ xh,
                         const float* __restrict__ wq, __half* __restrict__ wqT)
{
    const int bid = blockIdx.x;
    if (bid < WQ_BLOCKS) {
        const int K = CDIM, N = C3;
        const int nb32 = N / 32;
        const int n0 = (bid % nb32) * 32;
        const int k0 = (bid / nb32) * 32;
        __shared__ float tile[32][33];
        const int tx = threadIdx.x & 31;
        const int ty = threadIdx.x >> 5;
        #pragma unroll
        for (int i = 0; i < 32; i += 8)
            tile[ty + i][tx] = wq[(size_t)(k0 + ty + i) * N + n0 + tx];
        __syncthreads();
        #pragma unroll
        for (int i = 0; i < 32; i += 8)
            wqT[(size_t)(n0 + ty + i) * K + k0 + tx] = __float2half_rn(tile[tx][ty + i]);
    } else {
        const int i = (bid - WQ_BLOCKS) * 256 + threadIdx.x;
        if (i >= XC_N8) return;
        float4 v0 = ((const float4*)x)[2 * i];
        float4 v1 = ((const float4*)x)[2 * i + 1];
        uint4 o;
        o.x = pack_h2(v0.x, v0.y);
        o.y = pack_h2(v0.z, v0.w);
        o.z = pack_h2(v1.x, v1.y);
        o.w = pack_h2(v1.z, v1.w);
        ((uint4*)xh)[i] = o;
    }
}

// ---------------------------------------------------------------------------
// Pre-pass B (stream 1): Wout^T (transpose+fp16)
// ---------------------------------------------------------------------------
__global__ __launch_bounds__(256)
void wtrans_kernel(const float* __restrict__ in, __half* __restrict__ out, int K, int N)
{
    __shared__ float tile[32][33];
    const int k0 = blockIdx.y * 32;
    const int n0 = blockIdx.x * 32;
    const int tx = threadIdx.x & 31;
    const int ty = threadIdx.x >> 5;
    #pragma unroll
    for (int i = 0; i < 32; i += 8)
        tile[ty + i][tx] = in[(size_t)(k0 + ty + i) * N + n0 + tx];
    __syncthreads();
    #pragma unroll
    for (int i = 0; i < 32; i += 8)
        out[(size_t)(n0 + ty + i) * K + k0 + tx] = __float2half_rn(tile[tx][ty + i]);
}

// ---------------------------------------------------------------------------
// V transpose (stream 1, after GEMM V-part): g_vT[b][h][d][t]
// ---------------------------------------------------------------------------
__global__ __launch_bounds__(256)
void vtrans_kernel(const __half* __restrict__ qkvh, __half* __restrict__ vT)
{
    __shared__ __half tile[64][68];
    const int tb = blockIdx.x * 64;
    const int bh = blockIdx.y;
    const int b  = bh >> 4;
    const int h  = bh & 15;
    const int tid = threadIdx.x;
    const int rr = tid >> 4;
    const int c4 = (tid & 15) * 4;
    #pragma unroll
    for (int it = 0; it < 4; it++) {
        const int tt = it * 16 + rr;
        const __half* src = qkvh + (size_t)(b * SEQ + tb + tt) * C3 + 2 * CDIM + h * HDIM + c4;
        uint2 v = *(const uint2*)src;
        *(uint2*)&tile[tt][c4] = v;
    }
    __syncthreads();
    #pragma unroll
    for (int it = 0; it < 4; it++) {
        const int d = it * 16 + rr;
        __half vals[4];
        #pragma unroll
        for (int q = 0; q < 4; q++) vals[q] = tile[c4 + q][d];
        __half* dst = vT + ((size_t)(b * NHEAD + h) * HDIM + d) * SEQ + tb + c4;
        *(uint2*)dst = *(uint2*)vals;
    }
}

// ---------------------------------------------------------------------------
// fp16 mma GEMM + bias (R15 proven version) with column-offset param.
// C[M,N] = A[M,K] @ Bt[N,K]^T + bias[N]
// ---------------------------------------------------------------------------
#define GBM 128
#define GBN 128
#define GBK 64
#define T_STRIDE 72
#define TILE_HALVES (128 * T_STRIDE)
#define STG_HALVES (2 * TILE_HALVES)
#define GEMM_SMEM (3 * STG_HALVES * 2)

template<bool RND>
__global__ __launch_bounds__(256)
void gemm_h_kernel(const __half* __restrict__ A,
                   const __half* __restrict__ Bt,
                   const float* __restrict__ bias,
                   void* __restrict__ Cv,
                   int M, int N, int K, int col0)
{
    extern __shared__ char smem_raw[];
    __half* smem = (__half*)smem_raw;
    const int tid = threadIdx.x;
    const int wid = tid >> 5;
    const int l   = tid & 31;
    const int warpM = wid >> 2;
    const int warpN = wid & 3;
    const int g = l >> 2;
    const int t = l & 3;
    const int rowbase = blockIdx.y * GBM;
    const int colbase = (blockIdx.x + col0) * GBN;

    const uint32_t smb = smem_u32(smem);

    float acc[4][4][4];
    #pragma unroll
    for (int i = 0; i < 4; i++)
        #pragma unroll
        for (int j = 0; j < 4; j++)
            #pragma unroll
            for (int q = 0; q < 4; q++) acc[i][j][q] = 0.f;

    const int S = K / GBK;

    auto load_stage = [&](int stg, int k0) {
        const uint32_t sa = smb + (uint32_t)(stg * STG_HALVES) * 2;
        const uint32_t sb = sa + (uint32_t)TILE_HALVES * 2;
        #pragma unroll
        for (int it = 0; it < 4; it++) {
            const int idx = it * 256 + tid;
            const int r  = idx >> 3;
            const int c8 = (idx & 7) * 8;
            CP_ASYNC16(sa + (uint32_t)(r * T_STRIDE + c8) * 2,
                       A + (size_t)(rowbase + r) * K + k0 + c8);
            CP_ASYNC16(sb + (uint32_t)(r * T_STRIDE + c8) * 2,
                       Bt + (size_t)(colbase + r) * K + k0 + c8);
        }
        CP_COMMIT();
    };

    load_stage(0, 0);
    load_stage(1, GBK);

    const int arow0 = warpM * 64 + g;
    const int bcol0 = warpN * 32 + g;

    for (int s = 0; s < S; s++) {
        if (s + 1 < S) { CP_WAIT1(); } else { CP_WAIT0(); }
        __syncthreads();
        if (s + 2 < S) load_stage((s + 2) % 3, (s + 2) * GBK);

        const __half* as = smem + (s % 3) * STG_HALVES;
        const __half* bs = as + TILE_HALVES;
        #pragma unroll
        for (int ks = 0; ks < 4; ks++) {
            const int kk = ks * 16 + 2 * t;
            uint32_t af[4][4], bf[4][2];
            #pragma unroll
            for (int i = 0; i < 4; i++) {
                const int r = arow0 + i * 16;
                af[i][0] = *(const uint32_t*)(as + (r    ) * T_STRIDE + kk);
                af[i][1] = *(const uint32_t*)(as + (r + 8) * T_STRIDE + kk);
                af[i][2] = *(const uint32_t*)(as + (r    ) * T_STRIDE + kk + 8);
                af[i][3] = *(const uint32_t*)(as + (r + 8) * T_STRIDE + kk + 8);
            }
            #pragma unroll
            for (int j = 0; j < 4; j++) {
                const int n = bcol0 + j * 8;
                bf[j][0] = *(const uint32_t*)(bs + n * T_STRIDE + kk);
                bf[j][1] = *(const uint32_t*)(bs + n * T_STRIDE + kk + 8);
            }
            #pragma unroll
            for (int i = 0; i < 4; i++)
                #pragma unroll
                for (int j = 0; j < 4; j++)
                    mma_f16(acc[i][j], af[i], bf[j][0], bf[j][1]);
        }
    }

    const int erow = rowbase + warpM * 64 + g;
    const int ecol = colbase + warpN * 32 + 2 * t;
    #pragma unroll
    for (int i = 0; i < 4; i++) {
        #pragma unroll
        for (int j = 0; j < 4; j++) {
            const int r0 = erow + i * 16;
            const int c0 = ecol + j * 8;
            const float b0 = bias[c0], b1 = bias[c0 + 1];
            if (RND) {
                __half* C = (__half*)Cv;
                *(uint32_t*)(C + (size_t)r0 * N + c0)       = pack_h2(acc[i][j][0] + b0, acc[i][j][1] + b1);
                *(uint32_t*)(C + (size_t)(r0 + 8) * N + c0) = pack_h2(acc[i][j][2] + b0, acc[i][j][3] + b1);
            } else {
                float* C = (float*)Cv;
                float2 v0 = { acc[i][j][0] + b0, acc[i][j][1] + b1 };
                float2 v1 = { acc[i][j][2] + b0, acc[i][j][3] + b1 };
                *(float2*)(C + (size_t)r0 * N + c0)       = v0;
                *(float2*)(C + (size_t)(r0 + 8) * N + c0) = v1;
            }
        }
    }
}

// ---------------------------------------------------------------------------
// fp16 flash attention (R15 data paths) with 3-STAGE K/V ring and ONE
// barrier per tile. Register-direct P, f16x2 exp, ones-row l, packed
// max-reduce, vote-gated rescale.
// ---------------------------------------------------------------------------
#define AQ 128
#define AK 64
#define HS 72
#define K_HALVES (AK * HS)                 // 4608
#define V_HALVES (72 * HS)                 // 5184 (64 d rows + 8 pad rows)
#define KV_HALVES (K_HALVES + V_HALVES)    // 9792 per stage
#define ATTN_SMEM (3 * KV_HALVES * 2)      // 58752 B

__global__ __launch_bounds__(256, 2)
void attn_h_kernel(const __half* __restrict__ qkv, const __half* __restrict__ vT,
                   __half* __restrict__ out)
{
    extern __shared__ char smem_raw[];
    __half* sm = (__half*)smem_raw;

    const int qtile = gridDim.x - 1 - blockIdx.x;   // heavy tiles first
    const int h   = blockIdx.y;
    const int b   = blockIdx.z;
    const int tid = threadIdx.x;
    const int wid = tid >> 5;
    const int l   = tid & 31;
    const int g   = l >> 2;
    const int t   = l & 3;
    const int qb  = qtile * AQ;
    const int rg  = qb + wid * 16 + g;

    const float SC = 0.18033688011112042f;   // (1/sqrt(64)) * log2(e)
    const uint32_t smb = smem_u32(sm);

    auto load_kv = [&](int stg, int kb) {
        const uint32_t kbuf = smb + (uint32_t)(stg * KV_HALVES) * 2;
        const uint32_t vbuf = kbuf + (uint32_t)K_HALVES * 2;
        #pragma unroll
        for (int it = 0; it < 2; it++) {
            const int idx = it * 256 + tid;
            const int r  = idx >> 3;
            const int c8 = (idx & 7) * 8;
            CP_ASYNC16(kbuf + (uint32_t)(r * HS + c8) * 2,
                       qkv + (size_t)(b * SEQ + kb + r) * C3 + CDIM + h * HDIM + c8);
            CP_ASYNC16(vbuf + (uint32_t)(r * HS + c8) * 2,
                       vT + ((size_t)(b * NHEAD + h) * HDIM + r) * SEQ + kb + c8);
        }
        CP_COMMIT();
    };

    // Q fragments, softmax scale folded
    uint32_t qa[4][4];
    {
        const __half* Qr  = qkv + (size_t)(b * SEQ + rg    ) * C3 + h * HDIM;
        const __half* Qr8 = qkv + (size_t)(b * SEQ + rg + 8) * C3 + h * HDIM;
        #pragma unroll
        for (int ks = 0; ks < 4; ks++) {
            #pragma unroll
            for (int q = 0; q < 4; q++) {
                const __half* src = (q & 1) ? Qr8 : Qr;
                const int off = ks * 16 + 2 * t + ((q >> 1) ? 8 : 0);
                __half2 hv = *(const __half2*)(src + off);
                float2 fv = __half22float2(hv);
                qa[ks][q] = pack_h2(fv.x * SC, fv.y * SC);
            }
        }
    }

    // O[0..7] = output blocks; O[8] = l accumulator (ones-row of V)
    float O[9][4];
    #pragma unroll
    for (int nb = 0; nb < 9; nb++)
        #pragma unroll
        for (int q = 0; q < 4; q++) O[nb][q] = 0.f;
    float m0 = -INFINITY, m1 = -INFINITY;

    const int ntiles = (qb + AQ) / AK;

    load_kv(0, 0);
    if (ntiles > 1) load_kv(1, AK);

    // Init V pad rows 64-71 for all 3 stages (cp.async never writes them):
    // row 64 = 1.0 (ones for row-sum l), rows 65-71 = 0. 3stg x 8rows x 9chunks.
    if (tid < 216) {
        const int stage = tid / 72;
        const int w = tid % 72;
        const int row = 64 + w / 9;
        const int chunk = w % 9;
        const uint32_t ones2 = 0x3C003C00u;
        uint32_t v = (row == 64) ? ones2 : 0u;
        const uint32_t addr = smb + (uint32_t)(stage * KV_HALVES + K_HALVES + row * HS + chunk * 8) * 2;
        asm volatile("st.shared.v4.b32 [%0], {%1,%2,%3,%4};"
                     :: "r"(addr), "r"(v), "r"(v), "r"(v), "r"(v) : "memory");
    }

    for (int ti = 0; ti < ntiles; ti++) {
        if (ti + 1 < ntiles) { CP_WAIT1(); } else { CP_WAIT0(); }
        __syncthreads();
        if (ti + 2 < ntiles) load_kv((ti + 2) % 3, (ti + 2) * AK);

        const __half* Ksm = sm + (ti % 3) * KV_HALVES;
        const __half* Vsm = Ksm + K_HALVES;
        const int kb = ti * AK;

        // S = Q @ K^T (scaled, log2 domain)
        float sc[8][4];
        #pragma unroll
        for (int nb = 0; nb < 8; nb++) {
            sc[nb][0] = 0.f; sc[nb][1] = 0.f; sc[nb][2] = 0.f; sc[nb][3] = 0.f;
        }
        #pragma unroll
        for (int ks = 0; ks < 4; ks++) {
            const int kk = ks * 16 + 2 * t;
            #pragma unroll
            for (int nb = 0; nb < 8; nb++) {
                uint32_t bf0 = *(const uint32_t*)(Ksm + (nb * 8 + g) * HS + kk);
                uint32_t bf1 = *(const uint32_t*)(Ksm + (nb * 8 + g) * HS + kk + 8);
                mma_f16(sc[nb], qa[ks], bf0, bf1);
            }
        }

        const bool needmask = (kb + AK - 1) > (qb + wid * 16);
        float tm0 = -INFINITY, tm1 = -INFINITY;
        if (needmask) {
            #pragma unroll
            for (int nb = 0; nb < 8; nb++) {
                const int k0 = kb + nb * 8 + 2 * t;
                if (k0     > rg    ) sc[nb][0] = -INFINITY;
                if (k0 + 1 > rg    ) sc[nb][1] = -INFINITY;
                if (k0     > rg + 8) sc[nb][2] = -INFINITY;
                if (k0 + 1 > rg + 8) sc[nb][3] = -INFINITY;
                tm0 = fmaxf(tm0, fmaxf(sc[nb][0], sc[nb][1]));
                tm1 = fmaxf(tm1, fmaxf(sc[nb][2], sc[nb][3]));
            }
        } else {
            #pragma unroll
            for (int nb = 0; nb < 8; nb++) {
                tm0 = fmaxf(tm0, fmaxf(sc[nb][0], sc[nb][1]));
                tm1 = fmaxf(tm1, fmaxf(sc[nb][2], sc[nb][3]));
            }
        }
        {
            __half2 tm = __floats2half2_rn(tm0, tm1);
            __half2 o1 = __shfl_xor_sync(0xffffffffu, tm, 1);
            tm = __hmax2(tm, o1);
            __half2 o2 = __shfl_xor_sync(0xffffffffu, tm, 2);
            tm = __hmax2(tm, o2);
            float2 tmf = __half22float2(tm);
            tm0 = tmf.x; tm1 = tmf.y;
        }

        const float nm0 = fmaxf(m0, tm0);
        const float nm1 = fmaxf(m1, tm1);
        const bool upd = (nm0 != m0) || (nm1 != m1);
        if (__any_sync(0xffffffffu, upd)) {
            const uint32_t ch2 = exp2_h2(m0 - nm0, m1 - nm1);
            __half2 chh = *(__half2*)&ch2;
            float2 cf = __half22float2(chh);
            const float c0 = cf.x, c1 = cf.y;
            #pragma unroll
            for (int nb = 0; nb < 9; nb++) {
                O[nb][0] *= c0; O[nb][1] *= c0;
                O[nb][2] *= c1; O[nb][3] *= c1;
            }
            m0 = nm0; m1 = nm1;
        }

        // p = exp2(s - m) in fp16x2, direct A-fragments
        uint32_t pf[8][2];
        #pragma unroll
        for (int nb = 0; nb < 8; nb++) {
            pf[nb][0] = exp2_h2(sc[nb][0] - m0, sc[nb][1] - m0);
            pf[nb][1] = exp2_h2(sc[nb][2] - m1, sc[nb][3] - m1);
        }

        // O += P @ V  (blocks 0-7 = output dims, block 8 = l via ones-row)
        #pragma unroll
        for (int ks = 0; ks < 4; ks++) {
            const int kk = ks * 16 + 2 * t;
            uint32_t pa[4];
            pa[0] = pf[2 * ks    ][0];
            pa[1] = pf[2 * ks    ][1];
            pa[2] = pf[2 * ks + 1][0];
            pa[3] = pf[2 * ks + 1][1];
            #pragma unroll
            for (int nb = 0; nb < 9; nb++) {
                uint32_t bf0 = *(const uint32_t*)(Vsm + (nb * 8 + g) * HS + kk);
                uint32_t bf1 = *(const uint32_t*)(Vsm + (nb * 8 + g) * HS + kk + 8);
                mma_f16(O[nb], pa, bf0, bf1);
            }
        }
        // no trailing barrier: stage (ti+2)%3 overwrite is gated by the
        // NEXT tile's top barrier (its readers finished tile ti-1 before it)
    }

    const float l0 = __shfl_sync(0xffffffffu, O[8][0], l & 0x1c);
    const float l1 = __shfl_sync(0xffffffffu, O[8][2], l & 0x1c);
    const float inv0 = 1.f / l0;
    const float inv1 = 1.f / l1;

    __half* out0 = out + (size_t)(b * SEQ + rg    ) * CDIM + h * HDIM;
    __half* out8 = out + (size_t)(b * SEQ + rg + 8) * CDIM + h * HDIM;
    #pragma unroll
    for (int nb = 0; nb < 8; nb++) {
        *(uint32_t*)(out0 + nb * 8 + 2 * t) = pack_h2(O[nb][0] * inv0, O[nb][1] * inv0);
        *(uint32_t*)(out8 + nb * 8 + 2 * t) = pack_h2(O[nb][2] * inv1, O[nb][3] * inv1);
    }
}

// ---------------------------------------------------------------------------
// Launch: fork stream 1 to overlap Wout^T + vtrans under the QKV GEMM.
// ---------------------------------------------------------------------------
extern "C" void kernel_launch(void* const* d_in, const int* in_sizes, int n_in,
                              void* d_out, int out_size)
{
    const float* x    = (const float*)d_in[0];
    const float* Wqkv = (const float*)d_in[1];
    const float* bqkv = (const float*)d_in[2];
    const float* Wout = (const float*)d_in[3];
    const float* bout = (const float*)d_in[4];
    float* out = (float*)d_out;

    __half *qkvh, *vT, *attnh, *xh, *wqkvT, *woutT;
    cudaGetSymbolAddress((void**)&qkvh,  g_qkvh);
    cudaGetSymbolAddress((void**)&vT,    g_vT);
    cudaGetSymbolAddress((void**)&attnh, g_attnh);
    cudaGetSymbolAddress((void**)&xh,    g_xh);
    cudaGetSymbolAddress((void**)&wqkvT, g_wqkvT);
    cudaGetSymbolAddress((void**)&woutT, g_woutT);

    static cudaStream_t s1 = nullptr;
    static cudaEvent_t evRoot = nullptr, evV = nullptr, evS1 = nullptr;
    static bool init_done = false;
    if (!init_done) {
        cudaFuncSetAttribute(gemm_h_kernel<true>,  cudaFuncAttributeMaxDynamicSharedMemorySize, GEMM_SMEM);
        cudaFuncSetAttribute(gemm_h_kernel<false>, cudaFuncAttributeMaxDynamicSharedMemorySize, GEMM_SMEM);
        cudaFuncSetAttribute(attn_h_kernel, cudaFuncAttributeMaxDynamicSharedMemorySize, ATTN_SMEM);
        cudaStreamCreateWithFlags(&s1, cudaStreamNonBlocking);
        cudaEventCreateWithFlags(&evRoot, cudaEventDisableTiming);
        cudaEventCreateWithFlags(&evV,    cudaEventDisableTiming);
        cudaEventCreateWithFlags(&evS1,   cudaEventDisableTiming);
        init_done = true;
    }

    // Fork stream 1 off the main (capture) stream
    cudaEventRecord(evRoot, 0);
    cudaStreamWaitEvent(s1, evRoot, 0);

    // s1: Wout^T (independent of everything)
    {
        dim3 grid(CDIM / 32, CDIM / 32);
        wtrans_kernel<<<grid, 256, 0, s1>>>(Wout, woutT, CDIM, CDIM);
    }

    // s0: prepass (x -> fp16, Wqkv^T)
    prepass_main_kernel<<<PREM_BLOCKS, 256>>>(x, xh, Wqkv, wqkvT);

    // s0: QKV GEMM, V columns first (cols 2048..3071)
    {
        dim3 grid(8, MROWS / GBM);
        gemm_h_kernel<true><<<grid, 256, GEMM_SMEM>>>(xh, wqkvT, bqkv, qkvh, MROWS, C3, CDIM, 16);
    }
    cudaEventRecord(evV, 0);

    // s0: QKV GEMM, Q+K columns (cols 0..2047) — overlaps s1's vtrans
    {
        dim3 grid(16, MROWS / GBM);
        gemm_h_kernel<true><<<grid, 256, GEMM_SMEM>>>(xh, wqkvT, bqkv, qkvh, MROWS, C3, CDIM, 0);
    }

    // s1: V transpose (needs only the V columns)
    cudaStreamWaitEvent(s1, evV, 0);
    {
        dim3 grid(SEQ / 64, BATCH * NHEAD);
        vtrans_kernel<<<grid, 256, 0, s1>>>(qkvh, vT);
    }
    cudaEventRecord(evS1, s1);

    // s0: join, then attention + output projection
    cudaStreamWaitEvent(0, evS1, 0);
    {
        dim3 grid(SEQ / AQ, NHEAD, BATCH);
        attn_h_kernel<<<grid, 256, ATTN_SMEM>>>(qkvh, vT, attnh);
    }
    {
        dim3 grid(CDIM / GBN, MROWS / GBM);
        gemm_h_kernel<false><<<grid, 256, GEMM_SMEM>>>(attnh, woutT, bout, out, MROWS, CDIM, CDIM, 0);
    }
}